// round 1
// baseline (speedup 1.0000x reference)
#include <cuda_runtime.h>
#include <cstdint>

// VQ_88699664597022: VQ-VAE nearest-codeword lookup.
// x: [16*4096, 256] f32, embedding: [1024, 256] f32.
// out (f32): values_st [N*256] ++ indexes [N] (as float) ++ loss [1].

#define K_CB 1024
#define D_CW 256
#define TM   64     // tokens per CTA
#define TN   128    // codewords per chunk

__device__ float  g_enorm[K_CB];
__device__ double g_partial[4096];

// ---------------------------------------------------------------- e_norm
__global__ void vq_enorm(const float* __restrict__ emb) {
    int k = blockIdx.x * blockDim.x + threadIdx.x;
    if (k >= K_CB) return;
    const float4* row = reinterpret_cast<const float4*>(emb + (size_t)k * D_CW);
    float s = 0.f;
#pragma unroll 16
    for (int j = 0; j < D_CW / 4; ++j) {
        float4 v = row[j];
        s += v.x * v.x + v.y * v.y + v.z * v.z + v.w * v.w;
    }
    g_enorm[k] = s;
}

// ---------------------------------------------------------------- main
// smem layout (dynamic):
//   xs  : float [TM][260]       x tile (padded rows)
//   es  : float [32][130]       E^T chunk: es[dl][cw], cw contiguous
//   ens : float [TN]            e_norm for current chunk
//   sv  : float [TM][17]        per-tx best value
//   si  : int   [TM][17]        per-tx best index
//   fidx: int   [TM]            final index per token
extern __shared__ float s_mem[];

__global__ __launch_bounds__(256, 2) void vq_main(
    const float* __restrict__ x, const float* __restrict__ emb,
    float* __restrict__ out, int n_tok, long long out_size)
{
    float* xs   = s_mem;
    float* es   = xs + TM * 260;
    float* ens  = es + 32 * 130;
    float* sv   = ens + TN;
    int*   si   = (int*)(sv + TM * 17);
    int*   fidx = si + TM * 17;

    const int tid = threadIdx.x;
    const int tx  = tid & 15;
    const int ty  = tid >> 4;
    const int bm  = blockIdx.x;
    const int tok0 = bm * TM;

    // ---- load x tile (coalesced, float4) ----
    {
        int col4 = tid & 63;   // float4 column 0..63
        int tr   = tid >> 6;   // 0..3
        for (int t = tr; t < TM; t += 4) {
            float4 v = reinterpret_cast<const float4*>(
                x + (size_t)(tok0 + t) * D_CW)[col4];
            *reinterpret_cast<float4*>(&xs[t * 260 + col4 * 4]) = v;
        }
    }

    float bestv[4];
    int   besti[4];
#pragma unroll
    for (int i = 0; i < 4; ++i) { bestv[i] = 3.4e38f; besti[i] = 0; }

    for (int kk = 0; kk < K_CB; kk += TN) {
        double acc[4][4];
#pragma unroll
        for (int i = 0; i < 4; ++i)
#pragma unroll
            for (int j = 0; j < 4; ++j) acc[i][j] = 0.0;

        if (tid < TN) ens[tid] = g_enorm[kk + tid];

        for (int dd = 0; dd < D_CW; dd += 32) {
            __syncthreads();  // es/ens safe to overwrite; xs published (1st iter)
            // ---- fill es[dl][cw] = emb[kk+cw][dd+dl] (transpose) ----
            {
                int cw   = tid >> 1;
                int half = tid & 1;
                const float4* src = reinterpret_cast<const float4*>(
                    emb + (size_t)(kk + cw) * D_CW + dd + half * 16);
#pragma unroll
                for (int q = 0; q < 4; ++q) {
                    float4 v = src[q];
                    int dl = half * 16 + q * 4;
                    es[(dl + 0) * 130 + cw] = v.x;
                    es[(dl + 1) * 130 + cw] = v.y;
                    es[(dl + 2) * 130 + cw] = v.z;
                    es[(dl + 3) * 130 + cw] = v.w;
                }
            }
            __syncthreads();
            // ---- f32x2 rank-1 updates: 4 tokens x 4 cw-pairs ----
#pragma unroll 8
            for (int dl = 0; dl < 32; ++dl) {
                double e2[4];
#pragma unroll
                for (int j = 0; j < 4; ++j)
                    e2[j] = *reinterpret_cast<const double*>(
                        &es[dl * 130 + 2 * tx + 32 * j]);
#pragma unroll
                for (int i = 0; i < 4; ++i) {
                    float xv = xs[(ty * 4 + i) * 260 + dd + dl];
                    double xd;
                    asm("mov.b64 %0, {%1, %1};" : "=d"(xd) : "f"(xv));
#pragma unroll
                    for (int j = 0; j < 4; ++j)
                        asm("fma.rn.f32x2 %0, %1, %2, %0;"
                            : "+d"(acc[i][j]) : "d"(xd), "d"(e2[j]));
                }
            }
        }

        // ---- score chunk: score = |e|^2 - 2 x.e  (|x|^2 constant per token) ----
#pragma unroll
        for (int i = 0; i < 4; ++i) {
#pragma unroll
            for (int j = 0; j < 4; ++j) {
                float lo, hi;
                asm("mov.b64 {%0, %1}, %2;" : "=f"(lo), "=f"(hi) : "d"(acc[i][j]));
                int c0 = 2 * tx + 32 * j;
                float s0 = ens[c0]     - 2.f * lo;
                float s1 = ens[c0 + 1] - 2.f * hi;
                if (s0 < bestv[i]) { bestv[i] = s0; besti[i] = kk + c0; }
                if (s1 < bestv[i]) { bestv[i] = s1; besti[i] = kk + c0 + 1; }
            }
        }
        __syncthreads();  // protect ens/es before next chunk overwrites
    }

    // ---- cross-thread (tx) argmin reduce, tie-break on lower index ----
#pragma unroll
    for (int i = 0; i < 4; ++i) {
        int t = ty * 4 + i;
        sv[t * 17 + tx] = bestv[i];
        si[t * 17 + tx] = besti[i];
    }
    __syncthreads();
    if (tid < TM) {
        float bv = 3.4e38f; int bi = 1 << 30;
        for (int t = 0; t < 16; ++t) {
            float v = sv[tid * 17 + t];
            int  ix = si[tid * 17 + t];
            if (v < bv || (v == bv && ix < bi)) { bv = v; bi = ix; }
        }
        fidx[tid] = bi;
        long long ipos = (long long)n_tok * D_CW + tok0 + tid;
        if (ipos < out_size) out[ipos] = (float)bi;
    }
    __syncthreads();

    // ---- epilogue: gather values (coalesced) + loss partial ----
    double lsum = 0.0;
#pragma unroll 4
    for (int t = 0; t < TM; ++t) {
        int idx = fidx[t];
        float e  = emb[(size_t)idx * D_CW + tid];
        float xv = xs[t * 260 + tid];
        out[(size_t)(tok0 + t) * D_CW + tid] = e;
        float r = xv - e;
        lsum += (double)r * (double)r;
    }

    // deterministic block reduction of lsum
#pragma unroll
    for (int off = 16; off > 0; off >>= 1)
        lsum += __shfl_down_sync(0xffffffff, lsum, off);
    __shared__ double wsum[8];
    if ((tid & 31) == 0) wsum[tid >> 5] = lsum;
    __syncthreads();
    if (tid == 0) {
        double s = 0.0;
#pragma unroll
        for (int w = 0; w < 8; ++w) s += wsum[w];
        g_partial[bm] = s;
    }
}

// ---------------------------------------------------------------- finalize
__global__ void vq_finalize(float* __restrict__ out, int nblocks,
                            long long pos, double scale) {
    __shared__ double buf[256];
    double s = 0.0;
    for (int i = threadIdx.x; i < nblocks; i += 256) s += g_partial[i];
    buf[threadIdx.x] = s;
    __syncthreads();
    for (int off = 128; off > 0; off >>= 1) {
        if (threadIdx.x < off) buf[threadIdx.x] += buf[threadIdx.x + off];
        __syncthreads();
    }
    if (threadIdx.x == 0) out[pos] = (float)(buf[0] * scale);
}

// ---------------------------------------------------------------- launch
extern "C" void kernel_launch(void* const* d_in, const int* in_sizes, int n_in,
                              void* d_out, int out_size) {
    const float* x   = (const float*)d_in[0];
    const float* emb = (const float*)d_in[1];
    float* out = (float*)d_out;

    int nd      = in_sizes[0];      // 16*4096*256
    int n_tok   = nd / D_CW;        // 65536
    int nblocks = n_tok / TM;       // 1024

    vq_enorm<<<(K_CB + 255) / 256, 256>>>(emb);

    size_t shmem = (size_t)(TM * 260 + 32 * 130 + TN + TM * 17) * sizeof(float)
                 + (size_t)(TM * 17 + TM) * sizeof(int);
    cudaFuncSetAttribute(vq_main, cudaFuncAttributeMaxDynamicSharedMemorySize,
                         (int)shmem);
    vq_main<<<nblocks, 256, shmem>>>(x, emb, out, n_tok, (long long)out_size);

    long long lpos = (long long)nd + n_tok;
    if (lpos < (long long)out_size) {
        vq_finalize<<<1, 256>>>(out, nblocks, lpos, 1.1 / (double)nd);
    }
}

// round 8
// speedup vs baseline: 2.2018x; 2.2018x over previous
#include <cuda_runtime.h>
#include <cuda_bf16.h>
#include <cstdint>

// VQ_88699664597022 — bf16 mma.sync GEMM -> full score materialization ->
// guaranteed-shortlist exact (round-1 arithmetic) selection.
// out (f32): values [N*256] ++ indexes [N] ++ loss [1].

#define D_CW 256
#define K_CB 1024
#define NTOK 65536
#define MB   128          // tokens per CTA (kernel 1)
#define NCH  128          // codewords per n-chunk (8 chunks)
#define RPAD 264          // padded A/B row length (bf16) -> 528 B

__device__ __align__(16) __nv_bfloat16 g_ebf[K_CB * D_CW];
__device__ float  g_enorm[K_CB];
__device__ float  g_S[(size_t)NTOK * K_CB];   // approx scores, 268 MB
__device__ int    g_idx[NTOK];
__device__ double g_partial[NTOK / 64];

// ------------------------------------------------ helpers
__device__ __forceinline__ uint32_t smem_u32(const void* p) {
    uint32_t a;
    asm("{ .reg .u64 t; cvta.to.shared.u64 t, %1; cvt.u32.u64 %0, t; }"
        : "=r"(a) : "l"(p));
    return a;
}
__device__ __forceinline__ void ldmatrix4(uint32_t* r, uint32_t addr) {
    asm volatile("ldmatrix.sync.aligned.m8n8.x4.shared.b16 {%0,%1,%2,%3}, [%4];"
                 : "=r"(r[0]), "=r"(r[1]), "=r"(r[2]), "=r"(r[3]) : "r"(addr));
}
__device__ __forceinline__ void mma16816(float* c, const uint32_t* a,
                                         const uint32_t* b) {
    asm volatile(
        "mma.sync.aligned.m16n8k16.row.col.f32.bf16.bf16.f32 "
        "{%0,%1,%2,%3}, {%4,%5,%6,%7}, {%8,%9}, {%0,%1,%2,%3};"
        : "+f"(c[0]), "+f"(c[1]), "+f"(c[2]), "+f"(c[3])
        : "r"(a[0]), "r"(a[1]), "r"(a[2]), "r"(a[3]), "r"(b[0]), "r"(b[1]));
}
#define CP_ASYNC16(dst, src) \
    asm volatile("cp.async.cg.shared.global [%0], [%1], 16;" \
                 :: "r"(dst), "l"(src) : "memory")
#define CP_COMMIT() asm volatile("cp.async.commit_group;" ::: "memory")
#define CP_WAIT(n)  asm volatile("cp.async.wait_group %0;" :: "n"(n) : "memory")

// ------------------------------------------------ round-1 enorm (verbatim)
__global__ void vq_enorm(const float* __restrict__ emb) {
    int k = blockIdx.x * blockDim.x + threadIdx.x;
    if (k >= K_CB) return;
    const float4* row = reinterpret_cast<const float4*>(emb + (size_t)k * D_CW);
    float s = 0.f;
#pragma unroll 16
    for (int j = 0; j < D_CW / 4; ++j) {
        float4 v = row[j];
        s += v.x * v.x + v.y * v.y + v.z * v.z + v.w * v.w;
    }
    g_enorm[k] = s;
}

__global__ void vq_prep_e(const float* __restrict__ emb) {
    int k = blockIdx.x, d = threadIdx.x;
    g_ebf[k * D_CW + d] = __float2bfloat16(emb[(size_t)k * D_CW + d]);
}

// ------------------------------------------------ kernel 1: GEMM, write S
// smem: As [128][264] bf16 @0 (67584 B), Bs [2][128][264] @67584 (135168 B),
//       ens [1024] f32 @202752 (4096 B). total 206848 B.
__global__ void __launch_bounds__(256, 1)
vq_mma_k(const float* __restrict__ x)
{
    extern __shared__ char smem[];
    __nv_bfloat16* As = (__nv_bfloat16*)smem;
    float* ens = (float*)(smem + 202752);
    const uint32_t sb = smem_u32(smem);
    const uint32_t sA = sb, sB = sb + 67584;

    const int tid = threadIdx.x, wid = tid >> 5, lane = tid & 31;
    const int tok0 = blockIdx.x * MB;

#pragma unroll
    for (int i = 0; i < 4; ++i) ens[tid + i * 256] = g_enorm[tid + i * 256];

    // A: load x fp32, convert to bf16, padded rows
    {
        int row = tid >> 1, half = tid & 1;
        const float4* xr = reinterpret_cast<const float4*>(
            x + (size_t)(tok0 + row) * D_CW) + half * 32;
        __nv_bfloat16* dst = As + row * RPAD + half * 128;
#pragma unroll
        for (int q = 0; q < 16; ++q) {
            float4 v0 = xr[2 * q], v1 = xr[2 * q + 1];
            __nv_bfloat162 p0 = __floats2bfloat162_rn(v0.x, v0.y);
            __nv_bfloat162 p1 = __floats2bfloat162_rn(v0.z, v0.w);
            __nv_bfloat162 p2 = __floats2bfloat162_rn(v1.x, v1.y);
            __nv_bfloat162 p3 = __floats2bfloat162_rn(v1.z, v1.w);
            uint4 pk;
            pk.x = *(uint32_t*)&p0; pk.y = *(uint32_t*)&p1;
            pk.z = *(uint32_t*)&p2; pk.w = *(uint32_t*)&p3;
            *reinterpret_cast<uint4*>(dst + q * 8) = pk;
        }
    }

    // prefetch B chunk 0
    {
        uint32_t bbuf = sB;
#pragma unroll
        for (int t = 0; t < 16; ++t) {
            int id = tid + t * 256;
            int row = id >> 5, ck = id & 31;
            CP_ASYNC16(bbuf + row * 528 + ck * 16,
                       g_ebf + (size_t)row * D_CW + ck * 8);
        }
        CP_COMMIT();
    }

    const int rowA = tok0 + wid * 16 + (lane >> 2);      // acc[.][0..1]
    float* SrowA = g_S + (size_t)rowA * K_CB;
    float* SrowB = SrowA + (size_t)8 * K_CB;             // acc[.][2..3]

    for (int nc = 0; nc < 8; ++nc) {
        if (nc < 7) {
            uint32_t bbuf = sB + ((nc + 1) & 1) * 67584;
            const __nv_bfloat16* src = g_ebf + (size_t)(nc + 1) * NCH * D_CW;
#pragma unroll
            for (int t = 0; t < 16; ++t) {
                int id = tid + t * 256;
                int row = id >> 5, ck = id & 31;
                CP_ASYNC16(bbuf + row * 528 + ck * 16,
                           src + (size_t)row * D_CW + ck * 8);
            }
            CP_COMMIT();
            CP_WAIT(1);
        } else {
            CP_WAIT(0);
        }
        __syncthreads();

        float acc[16][4];
#pragma unroll
        for (int t = 0; t < 16; ++t)
#pragma unroll
            for (int j = 0; j < 4; ++j) acc[t][j] = 0.f;

        const uint32_t bBase = sB + (nc & 1) * 67584;
        const uint32_t aRow = sA + (wid * 16 + (lane & 15)) * 528
                            + ((lane >> 4) * 8) * 2;
        const uint32_t bRowOff = ((lane & 7) + ((lane >> 4) << 3)) * 528
                               + (((lane >> 3) & 1) << 3) * 2;
#pragma unroll
        for (int kk = 0; kk < 16; ++kk) {
            uint32_t a[4];
            ldmatrix4(a, aRow + kk * 32);
#pragma unroll
            for (int nt = 0; nt < 8; ++nt) {
                uint32_t b[4];
                ldmatrix4(b, bBase + nt * 16 * 528 + bRowOff + kk * 32);
                mma16816(acc[2 * nt],     a, b);
                mma16816(acc[2 * nt + 1], a, b + 2);
            }
        }

        // epilogue: s = enorm - 2*dot -> g_S  (each store = one 32B sector/quad)
        const int cb = nc * NCH + 2 * (lane & 3);
#pragma unroll
        for (int t = 0; t < 16; ++t) {
            int c = cb + t * 8;
            float2 e2 = *reinterpret_cast<const float2*>(ens + c);
            float2 sa, sbv;
            sa.x  = fmaf(-2.f, acc[t][0], e2.x);
            sa.y  = fmaf(-2.f, acc[t][1], e2.y);
            sbv.x = fmaf(-2.f, acc[t][2], e2.x);
            sbv.y = fmaf(-2.f, acc[t][3], e2.y);
            *reinterpret_cast<float2*>(SrowA + c) = sa;
            *reinterpret_cast<float2*>(SrowB + c) = sbv;
        }
        __syncthreads();
    }
}

// ------------------------------------------------ kernel 2: guaranteed select
// DELTA >= 2 * worst-case |approx - exact| (~2*1.4); shortlist provably
// contains the exact-arithmetic argmin. Rescore with round-1 fp32 chain.
#define DELTA_B 3.0f
__global__ void __launch_bounds__(256)
vq_select(const float* __restrict__ x, const float* __restrict__ emb,
          float* __restrict__ out, int n_tok)
{
    __shared__ int s_cnt[8];
    __shared__ int s_cand[8][128];
    const int wp = threadIdx.x >> 5, lane = threadIdx.x & 31;
    const int token = blockIdx.x * 8 + wp;

    const float4* S4 = reinterpret_cast<const float4*>(
        g_S + (size_t)token * K_CB) + lane * 8;
    float4 sv[8];
    float vmin = 3.4e38f;
#pragma unroll
    for (int j = 0; j < 8; ++j) {
        sv[j] = S4[j];
        vmin = fminf(vmin, fminf(fminf(sv[j].x, sv[j].y), fminf(sv[j].z, sv[j].w)));
    }
#pragma unroll
    for (int o = 16; o; o >>= 1)
        vmin = fminf(vmin, __shfl_xor_sync(0xffffffffu, vmin, o));

    if (lane == 0) s_cnt[wp] = 0;
    __syncwarp();
    const float thr = vmin + DELTA_B;
#pragma unroll
    for (int j = 0; j < 8; ++j) {
        int base = lane * 32 + j * 4;
        if (sv[j].x < thr) { int p = atomicAdd(&s_cnt[wp], 1); if (p < 128) s_cand[wp][p] = base; }
        if (sv[j].y < thr) { int p = atomicAdd(&s_cnt[wp], 1); if (p < 128) s_cand[wp][p] = base + 1; }
        if (sv[j].z < thr) { int p = atomicAdd(&s_cnt[wp], 1); if (p < 128) s_cand[wp][p] = base + 2; }
        if (sv[j].w < thr) { int p = atomicAdd(&s_cnt[wp], 1); if (p < 128) s_cand[wp][p] = base + 3; }
    }
    __syncwarp();
    int nc = min(s_cnt[wp], 128);

    int idx;
    if (nc == 1) {
        idx = s_cand[wp][0];
    } else {
        float bs = 3.4e38f; int bi = 0x7FFFFFFF;
        for (int b0 = 0; b0 < nc; b0 += 32) {
            int li = b0 + lane;
            float sc = 3.4e38f; int ci = 0x7FFFFFFF;
            if (li < nc) {
                ci = s_cand[wp][li];
                const float4* xr = reinterpret_cast<const float4*>(
                    x + (size_t)token * D_CW);
                const float4* er = reinterpret_cast<const float4*>(
                    emb + (size_t)ci * D_CW);
                float dot = 0.f;
#pragma unroll 8
                for (int q = 0; q < 64; ++q) {
                    float4 a = xr[q], e = er[q];
                    dot = fmaf(a.x, e.x, dot);
                    dot = fmaf(a.y, e.y, dot);
                    dot = fmaf(a.z, e.z, dot);
                    dot = fmaf(a.w, e.w, dot);
                }
                sc = g_enorm[ci] - 2.f * dot;
            }
#pragma unroll
            for (int o = 16; o; o >>= 1) {
                float os = __shfl_xor_sync(0xffffffffu, sc, o);
                int   oi = __shfl_xor_sync(0xffffffffu, ci, o);
                if (os < sc || (os == sc && oi < ci)) { sc = os; ci = oi; }
            }
            if (sc < bs || (sc == bs && ci < bi)) { bs = sc; bi = ci; }
        }
        idx = bi;
    }
    if (lane == 0) {
        g_idx[token] = idx;
        out[(size_t)n_tok * D_CW + token] = (float)idx;
    }
}

// ------------------------------------------------ gather values + loss
__global__ void vq_gather(const float* __restrict__ x,
                          const float* __restrict__ emb,
                          float* __restrict__ out) {
    int b = blockIdx.x, d = threadIdx.x;
    int t0 = b * 64;
    double ls = 0.0;
#pragma unroll 4
    for (int t = 0; t < 64; ++t) {
        int tok = t0 + t;
        int idx = g_idx[tok];
        float e  = emb[(size_t)idx * D_CW + d];
        float xv = x[(size_t)tok * D_CW + d];
        out[(size_t)tok * D_CW + d] = xv + (e - xv);   // reference ST rounding
        float r = xv - e;
        ls += (double)r * (double)r;
    }
#pragma unroll
    for (int o = 16; o > 0; o >>= 1) ls += __shfl_down_sync(0xffffffffu, ls, o);
    __shared__ double ws[8];
    if ((d & 31) == 0) ws[d >> 5] = ls;
    __syncthreads();
    if (d == 0) {
        double s = 0.0;
#pragma unroll
        for (int w = 0; w < 8; ++w) s += ws[w];
        g_partial[b] = s;
    }
}

__global__ void vq_finalize(float* __restrict__ out, int nblocks,
                            long long pos, double scale) {
    __shared__ double buf[256];
    double s = 0.0;
    for (int i = threadIdx.x; i < nblocks; i += 256) s += g_partial[i];
    buf[threadIdx.x] = s;
    __syncthreads();
    for (int off = 128; off > 0; off >>= 1) {
        if (threadIdx.x < off) buf[threadIdx.x] += buf[threadIdx.x + off];
        __syncthreads();
    }
    if (threadIdx.x == 0) out[pos] = (float)(buf[0] * scale);
}

// ------------------------------------------------ launch
extern "C" void kernel_launch(void* const* d_in, const int* in_sizes, int n_in,
                              void* d_out, int out_size) {
    const float* x   = (const float*)d_in[0];
    const float* emb = (const float*)d_in[1];
    float* out = (float*)d_out;

    int nd    = in_sizes[0];    // 65536*256
    int n_tok = nd / D_CW;      // 65536

    vq_enorm<<<(K_CB + 255) / 256, 256>>>(emb);
    vq_prep_e<<<K_CB, 256>>>(emb);

    size_t shmem = 206848;
    cudaFuncSetAttribute(vq_mma_k, cudaFuncAttributeMaxDynamicSharedMemorySize,
                         (int)shmem);
    vq_mma_k<<<n_tok / MB, 256, shmem>>>(x);

    vq_select<<<n_tok / 8, 256>>>(x, emb, out, n_tok);

    vq_gather<<<n_tok / 64, 256>>>(x, emb, out);

    long long lpos = (long long)nd + n_tok;
    if (lpos < (long long)out_size)
        vq_finalize<<<1, 256>>>(out, n_tok / 64, lpos, 1.1 / (double)nd);
}